// round 9
// baseline (speedup 1.0000x reference)
#include <cuda_runtime.h>
#include <cuda_bf16.h>
#include <cstdint>

// RFFT2d: x (32,1,1024,1024) fp32 -> out (32, 16384, 8, 5, 2) fp32
// 8x8 blocks, length-8 rFFT along each block row, scaled by 1/64.
//
// Dense warp loads (each LDG.128 covers 4 fully-consumed 128B lines) +
// __shfl redistribution to the owning thread -> halves read-side l1tex
// wavefronts vs the strided own-row loads. Outputs staged in smem
// (conflict-free STS, lanes own consecutive output rows) and drained by
// one 20KB cp.async.bulk per CTA.

#define TOTAL_ROWS (32u * 128u * 128u * 8u)  // 4,194,304
#define ROWS_PER_CTA 512u

__device__ __forceinline__ float4 shfl4(float4 v, unsigned src) {
    float4 r;
    r.x = __shfl_sync(0xffffffffu, v.x, src);
    r.y = __shfl_sync(0xffffffffu, v.y, src);
    r.z = __shfl_sync(0xffffffffu, v.z, src);
    r.w = __shfl_sync(0xffffffffu, v.w, src);
    return r;
}

__device__ __forceinline__ void rfft8_row(float4 v0, float4 v1, float* sm_row)
{
    float x0 = v0.x, x1 = v0.y, x2 = v0.z, x3 = v0.w;
    float x4 = v1.x, x5 = v1.y, x6 = v1.z, x7 = v1.w;

    const float s   = 0.70710678118654752440f;
    const float scl = 1.0f / 64.0f;

    float a = x0 + x4, b = x0 - x4;
    float c = x2 + x6, d = x2 - x6;
    float e = x1 + x5, f = x1 - x5;
    float g = x3 + x7, h = x3 - x7;

    float fmh = f - h;
    float fph = f + h;

    float X0r = (a + c) + (e + g);
    float X4r = (a + c) - (e + g);
    float X2r = a - c;
    float X2i = g - e;
    float sfmh = s * fmh;
    float sfph = s * fph;
    float X1r = b + sfmh;
    float X1i = -sfph - d;
    float X3r = b - sfmh;
    float X3i = d - sfph;

    float2* so = reinterpret_cast<float2*>(sm_row);
    so[0] = make_float2(X0r * scl, 0.0f);
    so[1] = make_float2(X1r * scl, X1i * scl);
    so[2] = make_float2(X2r * scl, X2i * scl);
    so[3] = make_float2(X3r * scl, X3i * scl);
    so[4] = make_float2(X4r * scl, 0.0f);
}

__global__ __launch_bounds__(256) void rfft8_kernel(
    const float* __restrict__ in, float* __restrict__ out)
{
    __shared__ __align__(16) float sm[ROWS_PER_CTA * 10u];  // 20480 B

    unsigned t = threadIdx.x;
    unsigned w = t >> 5;     // warp 0..7
    unsigned l = t & 31u;    // lane
    unsigned B = blockIdx.x; // 0..8191
    unsigned nbh = B >> 1;   // n*128 + bh

    // Dense load mapping: lane l reads float4 (l&7) of image row (l>>3)
    // within this warp-group's 4-block span. 8 lanes fully consume one
    // 128B line -> 4 wavefronts per LDG.128.
    const float4* in4 = reinterpret_cast<const float4*>(in);
    unsigned a00 = (nbh * 8u + (l >> 3)) * 256u        // image row (load0: r' 0..3)
                 + (B & 1u) * 128u + w * 16u           // warp g=0 span base (f4)
                 + (l & 7u);

    // All four loads issued up front (MLP = 4).
    float4 L0g0 = in4[a00];          // g0, image rows 0..3
    float4 L1g0 = in4[a00 + 1024u];  // g0, image rows 4..7 (+4 rows * 256 f4)
    float4 L0g1 = in4[a00 + 8u];     // g1 span = +4 blocks = +8 f4
    float4 L1g1 = in4[a00 + 1032u];

    // Gather routing: thread owns r_own = l&7, j0 = (l>>3)*2.
    // Source lane s = (r_own&3)*8 + j0 holds (r_own mod 4, j0) in load0 and
    // (r_own mod 4 + 4, j0) in load1; pick by r_own < 4.
    unsigned s0 = (l & 3u) * 8u + ((l >> 3) << 1);
    unsigned s1 = s0 + 1u;
    bool lo = (l & 4u) == 0u;  // r_own < 4

    // Group 0: rows rho = w*64 + l
    {
        float4 A = shfl4(L0g0, s0);
        float4 Bv = shfl4(L0g0, s1);
        float4 C = shfl4(L1g0, s0);
        float4 D = shfl4(L1g0, s1);
        float4 v0 = lo ? A : C;
        float4 v1 = lo ? Bv : D;
        rfft8_row(v0, v1, sm + (w * 64u + l) * 10u);
    }
    // Group 1: rows rho = w*64 + 32 + l
    {
        float4 A = shfl4(L0g1, s0);
        float4 Bv = shfl4(L0g1, s1);
        float4 C = shfl4(L1g1, s0);
        float4 D = shfl4(L1g1, s1);
        float4 v0 = lo ? A : C;
        float4 v1 = lo ? Bv : D;
        rfft8_row(v0, v1, sm + (w * 64u + 32u + l) * 10u);
    }

    // Make generic-proxy smem writes visible to the async (TMA) proxy.
    asm volatile("fence.proxy.async.shared::cta;" ::: "memory");
    __syncthreads();

    if (t == 0) {
        uint32_t saddr;
        asm("{ .reg .u64 tmp; cvta.to.shared.u64 tmp, %1; cvt.u32.u64 %0, tmp; }"
            : "=r"(saddr) : "l"(sm));
        float* dst = out + (size_t)B * (ROWS_PER_CTA * 10u);
        asm volatile(
            "cp.async.bulk.global.shared::cta.bulk_group [%0], [%1], %2;"
            :: "l"(dst), "r"(saddr), "r"(ROWS_PER_CTA * 40u) : "memory");
        asm volatile("cp.async.bulk.commit_group;" ::: "memory");
        asm volatile("cp.async.bulk.wait_group 0;" ::: "memory");
    }
}

extern "C" void kernel_launch(void* const* d_in, const int* in_sizes, int n_in,
                              void* d_out, int out_size)
{
    const float* x = (const float*)d_in[0];
    float* out = (float*)d_out;
    const unsigned threads = 256;
    const unsigned blocks = TOTAL_ROWS / ROWS_PER_CTA;  // 8192
    rfft8_kernel<<<blocks, threads>>>(x, out);
}